// round 8
// baseline (speedup 1.0000x reference)
#include <cuda_runtime.h>
#include <cstdint>

#define N 2304
#define BB 1024
#define FF 32
#define TEAM 72
#define NCTA (2 * TEAM)
#define NTHR 512

// device scratch (no allocation allowed)
__device__ float g_v[FF * N];       // forward shared state per frame
__device__ float g_z[FF * N];       // backward adjoint per frame
__device__ float g_keep[FF * N];    // keep mask
__device__ float g_vsum[TEAM];      // per-forward-CTA partial of sum_f sum(v_f)
__device__ int   g_cntF[64];        // forward-team barrier counters
__device__ int   g_cntB[64];        // backward-team barrier counters

__global__ void init_kernel() {
    int i = blockIdx.x * blockDim.x + threadIdx.x;
    if (i < FF * N) g_keep[i] = 1.0f;
    if (i < 64) { g_cntF[i] = 0; g_cntB[i] = 0; }
}

__global__ void scatter_kernel(const int* __restrict__ sel) {
    int i = threadIdx.x;
    if (i < 256) {
        int f = sel[3 * i];
        int node = sel[3 * i + 1] * 64 + sel[3 * i + 2];
        g_keep[f * N + node] = 0.0f;
    }
}

__device__ __forceinline__ void teambar(int* cnt, int s) {
    __threadfence();
    __syncthreads();
    if (threadIdx.x == 0) {
        atomicAdd(&cnt[s], 1);
        volatile int* c = &cnt[s];
        while (*c < TEAM) { }
        __threadfence();
    }
    __syncthreads();
}

__device__ __forceinline__ void l2pf(const void* p) {
    asm volatile("prefetch.global.L2 [%0];" :: "l"(p));
}

// Persistent solver: 144 co-resident CTAs split into two independent teams.
// CTAs 0..71:   forward chain  v_f = keep_f * (b_f + W[f-1] @ v_{f-1})
// CTAs 72..143: backward chain z_f = 1 + W[f]^T @ (keep_{f+1} * z_{f+1})
// Next step's weight slab is L2-prefetched during the reduce/barrier dead time.
__global__ void __launch_bounds__(NTHR, 1)
solve_kernel(const float* __restrict__ W, const float* __restrict__ B)
{
    __shared__ float s_v[N];
    __shared__ float s_red[NTHR];

    int tid = threadIdx.x;
    int cta = blockIdx.x;
    int warp = tid >> 5, lane = tid & 31;

    if (cta < TEAM) {
        // ================= FORWARD TEAM =================
        int r0 = cta * 32;                       // 32 rows per CTA
        float myacc = 0.f;

        // prefetch W[0] rows (used in step f=1) while v0/barrier happen
        {
            const char* base = (const char*)(W + (size_t)r0 * N);
            for (int i = tid; i < 2304; i += NTHR) l2pf(base + (size_t)i * 128);
        }

        // v0 = keep_0 * b_0
        if (tid < 32) {
            int row = r0 + tid;
            float v = g_keep[row] * B[row];
            g_v[row] = v;
            myacc += v;
        }
        teambar(g_cntF, 0);

        for (int f = 1; f < FF; ++f) {
            for (int n = tid; n < N; n += NTHR) s_v[n] = g_v[(f - 1) * N + n];
            __syncthreads();

            int ra = r0 + warp * 2;              // 16 warps x 2 rows
            const float4* wa = (const float4*)(W + ((size_t)(f - 1) * N + ra) * N);
            const float4* wb = (const float4*)(W + ((size_t)(f - 1) * N + ra + 1) * N);
            const float4* v4 = (const float4*)s_v;
            float acc0 = 0.f, acc1 = 0.f;
            #pragma unroll
            for (int i = 0; i < 18; ++i) {       // 576 float4 / 32 lanes
                int idx = lane + i * 32;
                float4 vv = v4[idx];
                float4 a4 = wa[idx];
                float4 b4 = wb[idx];
                acc0 += a4.x * vv.x + a4.y * vv.y + a4.z * vv.z + a4.w * vv.w;
                acc1 += b4.x * vv.x + b4.y * vv.y + b4.z * vv.z + b4.w * vv.w;
            }

            // prefetch next step's slab (W[f] rows r0..r0+31) into L2
            if (f < FF - 1) {
                const char* base = (const char*)(W + ((size_t)f * N + r0) * N);
                for (int i = tid; i < 2304; i += NTHR) l2pf(base + (size_t)i * 128);
            }

            #pragma unroll
            for (int o = 16; o; o >>= 1) {
                acc0 += __shfl_xor_sync(0xffffffffu, acc0, o);
                acc1 += __shfl_xor_sync(0xffffffffu, acc1, o);
            }
            if (lane == 0) {
                float va = g_keep[f * N + ra]     * (B[f * N + ra]     + acc0);
                float vb = g_keep[f * N + ra + 1] * (B[f * N + ra + 1] + acc1);
                g_v[f * N + ra]     = va;
                g_v[f * N + ra + 1] = vb;
                myacc += va + vb;
            }
            if (f < FF - 1) teambar(g_cntF, f);
        }

        // block-reduce myacc (fixed tree -> deterministic)
        #pragma unroll
        for (int o = 16; o; o >>= 1) myacc += __shfl_xor_sync(0xffffffffu, myacc, o);
        if (lane == 0) s_red[warp] = myacc;
        __syncthreads();
        if (tid == 0) {
            float t = 0.f;
            #pragma unroll
            for (int w = 0; w < 16; ++w) t += s_red[w];
            g_vsum[cta] = t;
        }
    } else {
        // ================= BACKWARD TEAM =================
        int id = cta - TEAM;
        int c0 = id * 32;                        // 32 cols per CTA

        // prefetch W[30] column slab (used in first step f=30)
        {
            const char* base = (const char*)(W + (size_t)30 * N * N + c0);
            for (int n = tid; n < N; n += NTHR) l2pf(base + (size_t)n * (N * 4));
        }

        if (tid < 32) g_z[31 * N + c0 + tid] = 1.0f;
        teambar(g_cntB, 0);

        for (int f = FF - 2; f >= 0; --f) {
            for (int n = tid; n < N; n += NTHR)
                s_v[n] = g_keep[(f + 1) * N + n] * g_z[(f + 1) * N + n];
            __syncthreads();

            int tx = tid & 31, ty = tid >> 5;    // 32 cols x 16 row-lanes
            const float* wp = W + (size_t)f * N * N + c0 + tx;
            float a0 = 0.f, a1 = 0.f, a2 = 0.f, a3 = 0.f;
            #pragma unroll 4
            for (int i = 0; i < 144; i += 4) {   // n = ty + 16*i
                int n0 = ty + (i + 0) * 16;
                int n1 = ty + (i + 1) * 16;
                int n2 = ty + (i + 2) * 16;
                int n3 = ty + (i + 3) * 16;
                a0 += wp[(size_t)n0 * N] * s_v[n0];
                a1 += wp[(size_t)n1 * N] * s_v[n1];
                a2 += wp[(size_t)n2 * N] * s_v[n2];
                a3 += wp[(size_t)n3 * N] * s_v[n3];
            }

            // prefetch next step's column slab (W[f-1] cols c0..c0+31)
            if (f > 0) {
                const char* base = (const char*)(W + (size_t)(f - 1) * N * N + c0);
                for (int n = tid; n < N; n += NTHR) l2pf(base + (size_t)n * (N * 4));
            }

            s_red[tid] = (a0 + a1) + (a2 + a3);
            __syncthreads();
            #pragma unroll
            for (int s2 = 256; s2 >= 32; s2 >>= 1) {
                if (tid < s2) s_red[tid] += s_red[tid + s2];
                __syncthreads();
            }
            if (tid < 32) g_z[f * N + c0 + tid] = 1.0f + s_red[tid];
            if (f > 0) teambar(g_cntB, 31 - f);
        }
    }
}

// out[b] = TOT - v_{cf}[cn] * z_{cf}[cn]
__global__ void final_kernel(const int* __restrict__ cand, float* __restrict__ out) {
    __shared__ float sr[128];
    int tid = threadIdx.x;
    // parallel reduce of g_vsum[0..71]
    float t = (tid < TEAM) ? g_vsum[tid] : 0.f;
    if (tid < 128) {
        #pragma unroll
        for (int o = 16; o; o >>= 1) t += __shfl_xor_sync(0xffffffffu, t, o);
        if ((tid & 31) == 0) sr[tid >> 5] = t;
    }
    __syncthreads();
    if (tid == 0) sr[0] = sr[0] + sr[1] + sr[2] + sr[3];
    __syncthreads();
    float TOT = sr[0];
    int cf = cand[3 * tid];
    int cn = cand[3 * tid + 1] * 64 + cand[3 * tid + 2];
    out[tid] = TOT - g_v[cf * N + cn] * g_z[cf * N + cn];
}

extern "C" void kernel_launch(void* const* d_in, const int* in_sizes, int n_in,
                              void* d_out, int out_size) {
    const float* weights = (const float*)d_in[0];
    const float* biases  = (const float*)d_in[1];
    const int*   sel     = (const int*)d_in[2];
    const int*   cand    = (const int*)d_in[3];
    float*       out     = (float*)d_out;

    init_kernel<<<(FF * N + 255) / 256, 256>>>();
    scatter_kernel<<<1, 256>>>(sel);
    solve_kernel<<<NCTA, NTHR>>>(weights, biases);
    final_kernel<<<1, BB>>>(cand, out);
}

// round 9
// speedup vs baseline: 1.2661x; 1.2661x over previous
#include <cuda_runtime.h>
#include <cstdint>

#define N 2304
#define BB 1024
#define FF 32
#define TEAM 72
#define NCTA (2 * TEAM)
#define NTHR 1024

// device scratch (no allocation allowed)
__device__ float g_v[FF * N];       // forward shared state per frame
__device__ float g_z[FF * N];       // backward adjoint per frame
__device__ float g_keep[FF * N];    // keep mask
__device__ float g_vsum[TEAM];      // per-forward-CTA partial of sum_f sum(v_f)
__device__ int   g_cntF[64];        // forward-team barrier counters
__device__ int   g_cntB[64];        // backward-team barrier counters

__global__ void init_kernel() {
    int i = blockIdx.x * blockDim.x + threadIdx.x;
    if (i < FF * N) g_keep[i] = 1.0f;
    if (i < 64) { g_cntF[i] = 0; g_cntB[i] = 0; }
}

__global__ void scatter_kernel(const int* __restrict__ sel) {
    int i = threadIdx.x;
    if (i < 256) {
        int f = sel[3 * i];
        int node = sel[3 * i + 1] * 64 + sel[3 * i + 2];
        g_keep[f * N + node] = 0.0f;
    }
}

__device__ __forceinline__ void teambar(int* cnt, int s) {
    __threadfence();
    __syncthreads();
    if (threadIdx.x == 0) {
        atomicAdd(&cnt[s], 1);
        volatile int* c = &cnt[s];
        while (*c < TEAM) { }
        __threadfence();
    }
    __syncthreads();
}

// Persistent solver: 144 co-resident CTAs (1/SM), two independent teams.
// CTAs 0..71:   forward chain  v_f = keep_f * (b_f + W[f-1] @ v_{f-1})
// CTAs 72..143: backward chain z_f = 1 + W[f]^T @ (keep_{f+1} * z_{f+1})
__global__ void __launch_bounds__(NTHR, 1)
solve_kernel(const float* __restrict__ W, const float* __restrict__ B)
{
    __shared__ float s_v[N];
    __shared__ float s_red[NTHR];

    int tid = threadIdx.x;
    int cta = blockIdx.x;
    int warp = tid >> 5, lane = tid & 31;

    if (cta < TEAM) {
        // ================= FORWARD TEAM =================
        int r0 = cta * 32;                       // 32 rows per CTA
        float myacc = 0.f;

        // v0 = keep_0 * b_0
        if (tid < 32) {
            int row = r0 + tid;
            float v = g_keep[row] * B[row];
            g_v[row] = v;
            myacc += v;
        }
        teambar(g_cntF, 0);

        for (int f = 1; f < FF; ++f) {
            for (int n = tid; n < N; n += NTHR) s_v[n] = g_v[(f - 1) * N + n];
            __syncthreads();

            int ra = r0 + warp;                  // 32 warps x 1 row
            const float4* wa = (const float4*)(W + ((size_t)(f - 1) * N + ra) * N);
            const float4* v4 = (const float4*)s_v;
            float acc0 = 0.f;
            #pragma unroll
            for (int i = 0; i < 18; ++i) {       // 576 float4 / 32 lanes
                int idx = lane + i * 32;
                float4 vv = v4[idx];
                float4 a4 = wa[idx];
                acc0 += a4.x * vv.x + a4.y * vv.y + a4.z * vv.z + a4.w * vv.w;
            }
            #pragma unroll
            for (int o = 16; o; o >>= 1)
                acc0 += __shfl_xor_sync(0xffffffffu, acc0, o);
            if (lane == 0) {
                float va = g_keep[f * N + ra] * (B[f * N + ra] + acc0);
                g_v[f * N + ra] = va;
                myacc += va;
            }
            if (f < FF - 1) teambar(g_cntF, f);
        }

        // block-reduce myacc (fixed tree -> deterministic)
        #pragma unroll
        for (int o = 16; o; o >>= 1) myacc += __shfl_xor_sync(0xffffffffu, myacc, o);
        if (lane == 0) s_red[warp] = myacc;
        __syncthreads();
        if (tid == 0) {
            float t = 0.f;
            #pragma unroll
            for (int w = 0; w < 32; ++w) t += s_red[w];
            g_vsum[cta] = t;
        }
    } else {
        // ================= BACKWARD TEAM =================
        int id = cta - TEAM;
        int c0 = id * 32;                        // 32 cols per CTA

        if (tid < 32) g_z[31 * N + c0 + tid] = 1.0f;
        teambar(g_cntB, 0);

        for (int f = FF - 2; f >= 0; --f) {
            for (int n = tid; n < N; n += NTHR)
                s_v[n] = g_keep[(f + 1) * N + n] * g_z[(f + 1) * N + n];
            __syncthreads();

            int tx = tid & 31, ty = tid >> 5;    // 32 cols x 32 row-lanes
            const float* wp = W + (size_t)f * N * N + c0 + tx;
            float a0 = 0.f, a1 = 0.f, a2 = 0.f, a3 = 0.f;
            #pragma unroll 4
            for (int i = 0; i < 72; i += 4) {    // n = ty + 32*i
                int n0 = ty + (i + 0) * 32;
                int n1 = ty + (i + 1) * 32;
                int n2 = ty + (i + 2) * 32;
                int n3 = ty + (i + 3) * 32;
                a0 += wp[(size_t)n0 * N] * s_v[n0];
                a1 += wp[(size_t)n1 * N] * s_v[n1];
                a2 += wp[(size_t)n2 * N] * s_v[n2];
                a3 += wp[(size_t)n3 * N] * s_v[n3];
            }
            s_red[tid] = (a0 + a1) + (a2 + a3);
            __syncthreads();
            #pragma unroll
            for (int s2 = 512; s2 >= 32; s2 >>= 1) {
                if (tid < s2) s_red[tid] += s_red[tid + s2];
                __syncthreads();
            }
            if (tid < 32) g_z[f * N + c0 + tid] = 1.0f + s_red[tid];
            if (f > 0) teambar(g_cntB, 31 - f);
        }
    }
}

// out[b] = TOT - v_{cf}[cn] * z_{cf}[cn]
__global__ void final_kernel(const int* __restrict__ cand, float* __restrict__ out) {
    __shared__ float sr[128];
    int tid = threadIdx.x;
    // parallel reduce of g_vsum[0..71]
    float t = (tid < TEAM) ? g_vsum[tid] : 0.f;
    if (tid < 128) {
        #pragma unroll
        for (int o = 16; o; o >>= 1) t += __shfl_xor_sync(0xffffffffu, t, o);
        if ((tid & 31) == 0) sr[tid >> 5] = t;
    }
    __syncthreads();
    if (tid == 0) sr[0] = sr[0] + sr[1] + sr[2] + sr[3];
    __syncthreads();
    float TOT = sr[0];
    int cf = cand[3 * tid];
    int cn = cand[3 * tid + 1] * 64 + cand[3 * tid + 2];
    out[tid] = TOT - g_v[cf * N + cn] * g_z[cf * N + cn];
}

extern "C" void kernel_launch(void* const* d_in, const int* in_sizes, int n_in,
                              void* d_out, int out_size) {
    const float* weights = (const float*)d_in[0];
    const float* biases  = (const float*)d_in[1];
    const int*   sel     = (const int*)d_in[2];
    const int*   cand    = (const int*)d_in[3];
    float*       out     = (float*)d_out;

    init_kernel<<<(FF * N + 255) / 256, 256>>>();
    scatter_kernel<<<1, 256>>>(sel);
    solve_kernel<<<NCTA, NTHR>>>(weights, biases);
    final_kernel<<<1, BB>>>(cand, out);
}